// round 14
// baseline (speedup 1.0000x reference)
#include <cuda_runtime.h>
#include <cuda_bf16.h>
#include <cuda_fp16.h>
#include <math.h>
#include <stdint.h>

#define NHEADS 16
#define NKVH   8
#define HDIM   64
#define QLEN   2048
#define CTXLEN 2048
#define TOT    4096
#define HID    1024
#define NSPLIT 4
#define SPLIT_KT 16

// fp32 intermediates
static __device__ float g_q [QLEN * NHEADS * HDIM];
static __device__ float g_k [TOT  * NKVH   * HDIM];

// attention split-K partials
static __device__ float g_po[NSPLIT][QLEN * NHEADS * HDIM];
static __device__ float g_pl[NSPLIT][QLEN * NHEADS];
static __device__ float g_pm[NSPLIT][QLEN * NHEADS];

// fp16 operand buffers
static __device__ __half c_hid_h[QLEN*HID], c_hid_l[QLEN*HID];
static __device__ __half c_tgt_h[CTXLEN*HID], c_tgt_l[CTXLEN*HID];
static __device__ __half c_wq_f [HID*1024];
static __device__ __half c_wk_f [HID*512];
static __device__ __half c_wv_f [HID*512];
static __device__ __half c_wo_f [1024*HID];
static __device__ __half c_ao_h [QLEN*1024], c_ao_l[QLEN*1024];

// attention operands: Q fp16 single, K fp16, V fp16
static __device__ __half c_q_f [QLEN*1024];
static __device__ __half c_k_f [TOT*512];
static __device__ __half c_v_f [TOT*512];

// ---------------- helpers ----------------
__device__ __forceinline__ uint32_t s2u(const void* p) {
    return (uint32_t)__cvta_generic_to_shared(p);
}
#define LDM_X4(r0,r1,r2,r3,a) \
    asm volatile("ldmatrix.sync.aligned.m8n8.x4.shared.b16 {%0,%1,%2,%3},[%4];" \
                 : "=r"(r0),"=r"(r1),"=r"(r2),"=r"(r3) : "r"(a))
#define LDM_X4T(r0,r1,r2,r3,a) \
    asm volatile("ldmatrix.sync.aligned.m8n8.x4.trans.shared.b16 {%0,%1,%2,%3},[%4];" \
                 : "=r"(r0),"=r"(r1),"=r"(r2),"=r"(r3) : "r"(a))
#define MMA_F16(c,a,b) \
    asm volatile("mma.sync.aligned.m16n8k16.row.col.f32.f16.f16.f32 " \
                 "{%0,%1,%2,%3},{%4,%5,%6,%7},{%8,%9},{%0,%1,%2,%3};" \
                 : "+f"(c[0]),"+f"(c[1]),"+f"(c[2]),"+f"(c[3]) \
                 : "r"(a[0]),"r"(a[1]),"r"(a[2]),"r"(a[3]),"r"(b[0]),"r"(b[1]))
#define CP16(dst,src) \
    asm volatile("cp.async.cg.shared.global [%0],[%1],16;" :: "r"(dst),"l"(src))
#define CP_COMMIT() asm volatile("cp.async.commit_group;")
#define CP_WAIT1()  asm volatile("cp.async.wait_group 1;")
#define CP_WAIT0()  asm volatile("cp.async.wait_group 0;")

__device__ __forceinline__ void split2h(float a, float b, uint32_t& hi, uint32_t& lo) {
    __half ha = __float2half_rn(a), hb = __float2half_rn(b);
    __half la = __float2half_rn(a - __half2float(ha));
    __half lb = __float2half_rn(b - __half2float(hb));
    hi = (uint32_t)__half_as_ushort(ha) | ((uint32_t)__half_as_ushort(hb) << 16);
    lo = (uint32_t)__half_as_ushort(la) | ((uint32_t)__half_as_ushort(lb) << 16);
}
__device__ __forceinline__ uint32_t packh2(float a, float b) {
    __half2 h = __floats2half2_rn(a, b);
    return *(uint32_t*)&h;
}

// ---------------- fused activation convert: hidden + target -> hi/lo fp16 ----
__global__ void cvt_acts(const float* __restrict__ hid, const float* __restrict__ tgt) {
    int base = (blockIdx.x * blockDim.x + threadIdx.x) * 4;
    const int n1 = QLEN * HID;
    const float* src; __half *hi, *lo; int off;
    if (base < n1) { src = hid; hi = c_hid_h; lo = c_hid_l; off = base; }
    else {
        off = base - n1;
        if (off >= CTXLEN * HID) return;
        src = tgt; hi = c_tgt_h; lo = c_tgt_l;
    }
    float4 v = *(const float4*)(src + off);
    uint32_t h0, l0, h1, l1;
    split2h(v.x, v.y, h0, l0);
    split2h(v.z, v.w, h1, l1);
    *(uint2*)(hi + off) = make_uint2(h0, h1);
    *(uint2*)(lo + off) = make_uint2(l0, l1);
}

// ---------------- fused weight convert ----------------
__global__ void cvt_wts(const float* __restrict__ Wq, const float* __restrict__ Wk,
                        const float* __restrict__ Wv, const float* __restrict__ Wo) {
    int base = (blockIdx.x * blockDim.x + threadIdx.x) * 4;
    const int nq = HID*1024, nk = HID*512, nv = HID*512, no = 1024*HID;
    const float* src; __half* dst; int off;
    if      (base < nq)              { src = Wq; dst = c_wq_f; off = base; }
    else if (base < nq+nk)           { src = Wk; dst = c_wk_f; off = base - nq; }
    else if (base < nq+nk+nv)        { src = Wv; dst = c_wv_f; off = base - nq - nk; }
    else if (base < nq+nk+nv+no)     { src = Wo; dst = c_wo_f; off = base - nq - nk - nv; }
    else return;
    float4 v = *(const float4*)(src + off);
    *(uint2*)(dst + off) = make_uint2(packh2(v.x, v.y), packh2(v.z, v.w));
}

// ---------------- tensor-core GEMM: fp16 2-term, occ=2 ----------
#define ASTR 40
#define BSTR 136
#define STAGEH (2*128*ASTR + 32*BSTR)
#define GEMM_SMEM_BYTES (2 * STAGEH * 2)

__device__ __forceinline__ void gemm_body(
    const __half* __restrict__ Ahi, const __half* __restrict__ Alo,
    const __half* __restrict__ Bf,
    float* __restrict__ C, __half* __restrict__ Ch,
    int N, int K, int bm, int bn, __half* sm)
{
    int tid = threadIdx.x;
    int lane = tid & 31, warp = tid >> 5;
    int wm = warp >> 2, wn = warp & 3;
    int lr = lane >> 2, lc = lane & 3;

    auto AsH = [&](int s) { return sm + s*STAGEH; };
    auto AsL = [&](int s) { return sm + s*STAGEH + 128*ASTR; };
    auto BsF = [&](int s) { return sm + s*STAGEH + 2*128*ASTR; };

    int arow = tid >> 2, aseg = tid & 3;
    int brow = tid >> 3, bseg = tid & 7;

    auto load_stage = [&](int s, int k0) {
        __half *ah = AsH(s), *al = AsL(s), *bf = BsF(s);
        #pragma unroll
        for (int r = 0; r < 2; r++) {
            int m = arow + r * 64;
            size_t g = (size_t)(bm + m) * K + k0 + aseg * 8;
            CP16(s2u(ah + m*ASTR + aseg*8), Ahi + g);
            CP16(s2u(al + m*ASTR + aseg*8), Alo + g);
        }
        #pragma unroll
        for (int r = 0; r < 2; r++) {
            int seg = bseg + r * 8;
            size_t g = (size_t)(k0 + brow) * N + bn + seg * 8;
            CP16(s2u(bf + brow*BSTR + seg*8), Bf + g);
        }
        CP_COMMIT();
    };

    float acc[4][4][4] = {};
    int T = K / 32;
    load_stage(0, 0);

    for (int t = 0; t < T; t++) {
        if (t + 1 < T) { load_stage((t + 1) & 1, (t + 1) * 32); CP_WAIT1(); }
        else           { CP_WAIT0(); }
        __syncthreads();
        __half *ah_ = AsH(t & 1), *al_ = AsL(t & 1), *bf_ = BsF(t & 1);
        #pragma unroll
        for (int ks = 0; ks < 2; ks++) {
            int kb = ks * 16;
            uint32_t ah[4][4], al[4][4], bf[4][2];
            #pragma unroll
            for (int mf = 0; mf < 4; mf++) {
                int r = wm*64 + mf*16 + (lane & 15);
                int c = kb + (lane >> 4) * 8;
                LDM_X4(ah[mf][0], ah[mf][1], ah[mf][2], ah[mf][3], s2u(ah_ + r*ASTR + c));
                LDM_X4(al[mf][0], al[mf][1], al[mf][2], al[mf][3], s2u(al_ + r*ASTR + c));
            }
            #pragma unroll
            for (int nfp = 0; nfp < 2; nfp++) {
                int r = kb + (lane & 7) + 8 * ((lane >> 3) & 1);
                int c = wn*32 + nfp*16 + (lane >> 4) * 8;
                LDM_X4T(bf[nfp*2][0], bf[nfp*2][1], bf[nfp*2+1][0], bf[nfp*2+1][1],
                        s2u(bf_ + r*BSTR + c));
            }
            #pragma unroll
            for (int mf = 0; mf < 4; mf++)
                #pragma unroll
                for (int nf = 0; nf < 4; nf++) {
                    MMA_F16(acc[mf][nf], al[mf], bf[nf]);
                    MMA_F16(acc[mf][nf], ah[mf], bf[nf]);
                }
        }
        __syncthreads();
    }
    if (Ch) {
        #pragma unroll
        for (int mf = 0; mf < 4; mf++) {
            int r0 = bm + wm*64 + mf*16 + lr;
            #pragma unroll
            for (int nf = 0; nf < 4; nf++) {
                int c0 = bn + wn*32 + nf*8 + 2*lc;
                *(uint32_t*)&Ch[(size_t)r0 * N + c0]       = packh2(acc[mf][nf][0], acc[mf][nf][1]);
                *(uint32_t*)&Ch[(size_t)(r0 + 8) * N + c0] = packh2(acc[mf][nf][2], acc[mf][nf][3]);
            }
        }
    } else {
        #pragma unroll
        for (int mf = 0; mf < 4; mf++) {
            int r0 = bm + wm*64 + mf*16 + lr;
            #pragma unroll
            for (int nf = 0; nf < 4; nf++) {
                int c0 = bn + wn*32 + nf*8 + 2*lc;
                *(float2*)&C[(size_t)r0 * N + c0]       = make_float2(acc[mf][nf][0], acc[mf][nf][1]);
                *(float2*)&C[(size_t)(r0 + 8) * N + c0] = make_float2(acc[mf][nf][2], acc[mf][nf][3]);
            }
        }
    }
}

__global__ __launch_bounds__(256, 2)
void gemm_f2(const __half* Ahi, const __half* Alo, const __half* Bf,
             float* C, int N, int K) {
    extern __shared__ __half gsm[];
    gemm_body(Ahi, Alo, Bf, C, nullptr, N, K, blockIdx.y * 128, blockIdx.x * 128, gsm);
}

// z = 0: Kctx(fp32), 1: Knoise(fp32), 2: Vctx(fp16 direct), 3: Vnoise(fp16 direct)
__global__ __launch_bounds__(256, 2)
void kvproj_f2(float* __restrict__ Kout) {
    extern __shared__ __half gsm[];
    int z = blockIdx.z;
    const __half *Ah = (z & 1) ? c_hid_h : c_tgt_h;
    const __half *Al = (z & 1) ? c_hid_l : c_tgt_l;
    const __half *Bf = (z < 2) ? c_wk_f : c_wv_f;
    size_t off = (z & 1) ? (size_t)QLEN * 512 : 0;
    float*  C  = (z < 2) ? Kout + off : nullptr;
    __half* Ch = (z < 2) ? nullptr : c_v_f + off;
    gemm_body(Ah, Al, Bf, C, Ch, 512, HID, blockIdx.y * 128, blockIdx.x * 128, gsm);
}

// ---------------- RMS-norm + RoPE: q,k -> single fp16 ----------
__global__ void norm_rope(const float* __restrict__ cosb, const float* __restrict__ sinb,
                          const float* __restrict__ qw,   const float* __restrict__ kw) {
    int warp = (blockIdx.x * blockDim.x + threadIdx.x) >> 5;
    int lane = threadIdx.x & 31;
    const float* src; size_t off; int pos; const float* w; bool isq;
    if (warp < QLEN * NHEADS) {
        int row = warp / NHEADS, h = warp % NHEADS;
        off = (size_t)row * 1024 + h * HDIM;
        src = g_q + off; pos = CTXLEN + row; w = qw; isq = true;
    } else {
        int v2 = warp - QLEN * NHEADS;
        int row = v2 / NKVH, h = v2 % NKVH;
        off = (size_t)row * 512 + h * HDIM;
        src = g_k + off; pos = row; w = kw; isq = false;
    }
    float x0 = src[lane], x1 = src[lane + 32];
    float ss = x0*x0 + x1*x1;
    #pragma unroll
    for (int o = 16; o; o >>= 1) ss += __shfl_xor_sync(0xffffffffu, ss, o);
    float r = rsqrtf(ss * (1.0f/64.0f) + 1e-6f);
    x0 *= r * w[lane];
    x1 *= r * w[lane + 32];
    float c0 = cosb[(size_t)pos*HDIM + lane], c1 = cosb[(size_t)pos*HDIM + lane + 32];
    float s0 = sinb[(size_t)pos*HDIM + lane], s1 = sinb[(size_t)pos*HDIM + lane + 32];
    float y0 = x0 * c0 - x1 * s0;
    float y1 = x1 * c1 + x0 * s1;
    __half* dst = isq ? c_q_f : c_k_f;
    dst[off + lane]      = __float2half_rn(y0);
    dst[off + lane + 32] = __float2half_rn(y1);
}

// ---------------- flash attention: fp16 QK 1-term, PV 1-term, split-K x4 ------
#define PADH 72
#define Q_BYTES   (4608*2)
#define WORK_OFF  Q_BYTES
#define WORK_BYTES 69632
#define STATS_OFF (WORK_OFF + WORK_BYTES)
#define ATTN_SMEM_BYTES (STATS_OFF + 2048)

__global__ __launch_bounds__(256, 2)
void attn_kernel(const float* __restrict__ mask,
                 const float* __restrict__ tree_bias,
                 const int*   __restrict__ relmap) {
    extern __shared__ char asmem[];
    __half* Qf = (__half*)asmem;
    __half* stg = (__half*)(asmem + WORK_OFF);
    float* red   = (float*)(asmem + WORK_OFF);
    float* mpart = (float*)(asmem + STATS_OFF);
    float* lpart = mpart + 256;

    int qb = blockIdx.x, h = blockIdx.y, sp = blockIdx.z;
    int kt0 = sp * SPLIT_KT;
    int kvh = h >> 1;
    int tid = threadIdx.x;
    int lane = tid & 31, warp = tid >> 5;
    int wm = warp >> 2, wn = warp & 3;
    int lr = lane >> 2, lc = lane & 3;

    {
        int row = tid >> 2;
        #pragma unroll
        for (int i = 0; i < 2; i++) {
            int seg = (tid & 3) + 4 * i;
            size_t g = (size_t)(qb*64 + row) * 1024 + h * HDIM + seg * 8;
            *(uint4*)&Qf[row*PADH + seg*8] = *(const uint4*)&c_q_f[g];
        }
    }

    int krow = tid >> 3, kseg = tid & 7;
    auto load_kv = [&](int s, int kt) {
        __half* Kf = stg + s*2*4608;
        __half* Vf = Kf + 4608;
        #pragma unroll
        for (int i = 0; i < 2; i++) {
            int kk = krow + 32*i;
            size_t g = (size_t)(kt*64 + kk) * 512 + kvh*HDIM + kseg*8;
            CP16(s2u(Kf + kk*PADH + kseg*8), c_k_f + g);
            CP16(s2u(Vf + kk*PADH + kseg*8), c_v_f + g);
        }
        CP_COMMIT();
    };

    float oacc[2][8][4] = {};
    float lacc[2][2] = {};
    float mrow[2][2] = {{-1e30f,-1e30f},{-1e30f,-1e30f}};

    load_kv(0, kt0);
    __syncthreads();

    for (int it = 0; it < SPLIT_KT; it++) {
        int kt = kt0 + it;
        CP_WAIT0();
        __syncthreads();
        if (it + 1 < SPLIT_KT) load_kv((it + 1) & 1, kt + 1);

        __half* Kf = stg + (it & 1)*2*4608;
        __half* Vf = Kf + 4608;

        // ---- S = Q @ K^T (single fp16 term) ----
        float s[2][2][4] = {};
        #pragma unroll
        for (int ks = 0; ks < 4; ks++) {
            int kb = ks * 16;
            uint32_t aq[2][4], bf[2][2];
            #pragma unroll
            for (int mf = 0; mf < 2; mf++) {
                int r = wm*32 + mf*16 + (lane & 15);
                int c = kb + (lane >> 4) * 8;
                LDM_X4(aq[mf][0], aq[mf][1], aq[mf][2], aq[mf][3], s2u(Qf + r*PADH + c));
            }
            {
                int r = wn*16 + (lane & 7) + 8 * (lane >> 4);
                int c = kb + 8 * ((lane >> 3) & 1);
                LDM_X4(bf[0][0], bf[0][1], bf[1][0], bf[1][1], s2u(Kf + r*PADH + c));
            }
            #pragma unroll
            for (int mf = 0; mf < 2; mf++)
                #pragma unroll
                for (int nf = 0; nf < 2; nf++)
                    MMA_F16(s[mf][nf], aq[mf], bf[nf]);
        }

        // ---- scale + mask + bias; warp-local online softmax ----
        int qg = qb * 64, kg = kt * 64;
        bool diag = (kt == 32 + qb);
        uint32_t pa[2][4];
        #pragma unroll
        for (int mf = 0; mf < 2; mf++) {
            int r0 = wm*32 + mf*16 + lr;
            #pragma unroll
            for (int nf = 0; nf < 2; nf++) {
                int c0 = wn*16 + nf*8 + 2*lc;
                float2 m0 = *(const float2*)&mask[(size_t)(qg + r0)     * TOT + kg + c0];
                float2 m1 = *(const float2*)&mask[(size_t)(qg + r0 + 8) * TOT + kg + c0];
                s[mf][nf][0] = s[mf][nf][0]*0.125f + m0.x;
                s[mf][nf][1] = s[mf][nf][1]*0.125f + m0.y;
                s[mf][nf][2] = s[mf][nf][2]*0.125f + m1.x;
                s[mf][nf][3] = s[mf][nf][3]*0.125f + m1.y;
                if (diag) {
                    s[mf][nf][0] += tree_bias[relmap[qb*4096 +  r0     *64 + c0    ] * NHEADS + h];
                    s[mf][nf][1] += tree_bias[relmap[qb*4096 +  r0     *64 + c0 + 1] * NHEADS + h];
                    s[mf][nf][2] += tree_bias[relmap[qb*4096 + (r0 + 8)*64 + c0    ] * NHEADS + h];
                    s[mf][nf][3] += tree_bias[relmap[qb*4096 + (r0 + 8)*64 + c0 + 1] * NHEADS + h];
                }
            }
            float mx0 = fmaxf(fmaxf(s[mf][0][0], s[mf][0][1]), fmaxf(s[mf][1][0], s[mf][1][1]));
            float mx1 = fmaxf(fmaxf(s[mf][0][2], s[mf][0][3]), fmaxf(s[mf][1][2], s[mf][1][3]));
            mx0 = fmaxf(mx0, __shfl_xor_sync(0xffffffffu, mx0, 1));
            mx0 = fmaxf(mx0, __shfl_xor_sync(0xffffffffu, mx0, 2));
            mx1 = fmaxf(mx1, __shfl_xor_sync(0xffffffffu, mx1, 1));
            mx1 = fmaxf(mx1, __shfl_xor_sync(0xffffffffu, mx1, 2));
            mx0 = fmaxf(mx0, mrow[mf][0]);
            mx1 = fmaxf(mx1, mrow[mf][1]);
            float sc0 = __expf(mrow[mf][0] - mx0);
            float sc1 = __expf(mrow[mf][1] - mx1);
            mrow[mf][0] = mx0; mrow[mf][1] = mx1;
            float p[2][4];
            #pragma unroll
            for (int nf = 0; nf < 2; nf++) {
                p[nf][0] = __expf(s[mf][nf][0] - mx0);
                p[nf][1] = __expf(s[mf][nf][1] - mx0);
                p[nf][2] = __expf(s[mf][nf][2] - mx1);
                p[nf][3] = __expf(s[mf][nf][3] - mx1);
            }
            lacc[mf][0] = lacc[mf][0]*sc0 + p[0][0]+p[0][1]+p[1][0]+p[1][1];
            lacc[mf][1] = lacc[mf][1]*sc1 + p[0][2]+p[0][3]+p[1][2]+p[1][3];
            #pragma unroll
            for (int nf = 0; nf < 8; nf++) {
                oacc[mf][nf][0] *= sc0; oacc[mf][nf][1] *= sc0;
                oacc[mf][nf][2] *= sc1; oacc[mf][nf][3] *= sc1;
            }
            pa[mf][0] = packh2(p[0][0], p[0][1]);
            pa[mf][1] = packh2(p[0][2], p[0][3]);
            pa[mf][2] = packh2(p[1][0], p[1][1]);
            pa[mf][3] = packh2(p[1][2], p[1][3]);
        }

        // ---- O += P @ V ----
        #pragma unroll
        for (int ng = 0; ng < 4; ng++) {
            uint32_t bv[2][2];
            int r = wn*16 + (lane & 7) + 8 * ((lane >> 3) & 1);
            int c = ng*16 + (lane >> 4) * 8;
            LDM_X4T(bv[0][0], bv[0][1], bv[1][0], bv[1][1], s2u(Vf + r*PADH + c));
            #pragma unroll
            for (int mf = 0; mf < 2; mf++)
                #pragma unroll
                for (int j = 0; j < 2; j++)
                    MMA_F16(oacc[mf][ng*2+j], pa[mf], bv[j]);
        }
    }

    // ---- cross-warp combine ----
    __syncthreads();
    #pragma unroll
    for (int mf = 0; mf < 2; mf++) {
        float l0 = lacc[mf][0], l1 = lacc[mf][1];
        l0 += __shfl_xor_sync(0xffffffffu, l0, 1);
        l0 += __shfl_xor_sync(0xffffffffu, l0, 2);
        l1 += __shfl_xor_sync(0xffffffffu, l1, 1);
        l1 += __shfl_xor_sync(0xffffffffu, l1, 2);
        if (lc == 0) {
            lpart[(wm*32 + mf*16 + lr    )*4 + wn] = l0;
            lpart[(wm*32 + mf*16 + lr + 8)*4 + wn] = l1;
            mpart[(wm*32 + mf*16 + lr    )*4 + wn] = mrow[mf][0];
            mpart[(wm*32 + mf*16 + lr + 8)*4 + wn] = mrow[mf][1];
        }
    }
    #pragma unroll
    for (int mf = 0; mf < 2; mf++) {
        int r0 = wm*32 + mf*16 + lr;
        #pragma unroll
        for (int nf = 0; nf < 8; nf++) {
            int c0 = nf*8 + 2*lc;
            *(float2*)&red[((size_t)wn*64 + r0    )*68 + c0] = make_float2(oacc[mf][nf][0], oacc[mf][nf][1]);
            *(float2*)&red[((size_t)wn*64 + r0 + 8)*68 + c0] = make_float2(oacc[mf][nf][2], oacc[mf][nf][3]);
        }
    }
    __syncthreads();

    {
        int row = tid >> 2, db = (tid & 3) * 16;
        float4 mp = *(float4*)&mpart[row*4];
        float M = fmaxf(fmaxf(mp.x, mp.y), fmaxf(mp.z, mp.w));
        float w0 = __expf(mp.x - M), w1 = __expf(mp.y - M);
        float w2 = __expf(mp.z - M), w3 = __expf(mp.w - M);
        float4 lp = *(float4*)&lpart[row*4];
        float lsum = w0*lp.x + w1*lp.y + w2*lp.z + w3*lp.w;
        size_t gbase = (size_t)(qb*64 + row) * 1024 + h*HDIM + db;
        #pragma unroll
        for (int j = 0; j < 4; j++) {
            int d = db + j*4;
            float4 a0 = *(float4*)&red[((size_t)0*64 + row)*68 + d];
            float4 a1 = *(float4*)&red[((size_t)1*64 + row)*68 + d];
            float4 a2 = *(float4*)&red[((size_t)2*64 + row)*68 + d];
            float4 a3 = *(float4*)&red[((size_t)3*64 + row)*68 + d];
            *(float4*)&g_po[sp][gbase + j*4] = make_float4(
                w0*a0.x + w1*a1.x + w2*a2.x + w3*a3.x,
                w0*a0.y + w1*a1.y + w2*a2.y + w3*a3.y,
                w0*a0.z + w1*a1.z + w2*a2.z + w3*a3.z,
                w0*a0.w + w1*a1.w + w2*a2.w + w3*a3.w);
        }
        if ((tid & 3) == 0) {
            g_pl[sp][(qb*64 + row)*16 + h] = lsum;
            g_pm[sp][(qb*64 + row)*16 + h] = M;
        }
    }
}

// ---------------- split-K combine (4 partials) -> c_ao fp16 hi/lo ----------------
__global__ void attn_combine() {
    int gw = (blockIdx.x * blockDim.x + threadIdx.x) >> 5;
    int lane = threadIdx.x & 31;
    if (gw >= QLEN * NHEADS) return;
    int row = gw >> 4, h = gw & 15;
    int il = row * 16 + h;
    float m0 = g_pm[0][il], m1 = g_pm[1][il], m2 = g_pm[2][il], m3 = g_pm[3][il];
    float M = fmaxf(fmaxf(m0, m1), fmaxf(m2, m3));
    float w0 = __expf(m0 - M), w1 = __expf(m1 - M);
    float w2 = __expf(m2 - M), w3 = __expf(m3 - M);
    float l = w0*g_pl[0][il] + w1*g_pl[1][il] + w2*g_pl[2][il] + w3*g_pl[3][il];
    float inv = 1.0f / l;
    size_t base = (size_t)row * 1024 + h * HDIM;
    float2 a0 = *(float2*)&g_po[0][base + 2*lane];
    float2 a1 = *(float2*)&g_po[1][base + 2*lane];
    float2 a2 = *(float2*)&g_po[2][base + 2*lane];
    float2 a3 = *(float2*)&g_po[3][base + 2*lane];
    float v0 = (w0*a0.x + w1*a1.x + w2*a2.x + w3*a3.x) * inv;
    float v1 = (w0*a0.y + w1*a1.y + w2*a2.y + w3*a3.y) * inv;
    uint32_t hi, lo;
    split2h(v0, v1, hi, lo);
    *(uint32_t*)&c_ao_h[base + 2*lane] = hi;
    *(uint32_t*)&c_ao_l[base + 2*lane] = lo;
}

// ---------------------------------------------------------------------------
extern "C" void kernel_launch(void* const* d_in, const int* in_sizes, int n_in,
                              void* d_out, int out_size) {
    const float* hidden = (const float*)d_in[0];
    const float* target = (const float*)d_in[1];
    const float* cosb   = (const float*)d_in[2];
    const float* sinb   = (const float*)d_in[3];
    const float* mask   = (const float*)d_in[4];
    const float* Wq     = (const float*)d_in[5];
    const float* Wk     = (const float*)d_in[6];
    const float* Wv     = (const float*)d_in[7];
    const float* Wo     = (const float*)d_in[8];
    const float* qw     = (const float*)d_in[9];
    const float* kw     = (const float*)d_in[10];
    const float* tb     = (const float*)d_in[11];
    const int*   rm     = (const int*)d_in[12];
    float* out = (float*)d_out;

    float *pq, *pk;
    cudaGetSymbolAddress((void**)&pq, g_q);
    cudaGetSymbolAddress((void**)&pk, g_k);

    __half *hidh,*hidl,*wqf,*wof,*aoh,*aol;
    cudaGetSymbolAddress((void**)&hidh, c_hid_h); cudaGetSymbolAddress((void**)&hidl, c_hid_l);
    cudaGetSymbolAddress((void**)&wqf,  c_wq_f);
    cudaGetSymbolAddress((void**)&wof,  c_wo_f);
    cudaGetSymbolAddress((void**)&aoh,  c_ao_h);  cudaGetSymbolAddress((void**)&aol,  c_ao_l);

    cvt_acts<<<((QLEN+CTXLEN)*HID/4 + 255)/256, 256>>>(hidden, target);
    cvt_wts<<<((HID*1024 + HID*512 + HID*512 + 1024*HID)/4 + 255)/256, 256>>>(Wq, Wk, Wv, Wo);

    cudaFuncSetAttribute(gemm_f2,   cudaFuncAttributeMaxDynamicSharedMemorySize, GEMM_SMEM_BYTES);
    cudaFuncSetAttribute(kvproj_f2, cudaFuncAttributeMaxDynamicSharedMemorySize, GEMM_SMEM_BYTES);

    gemm_f2<<<dim3(1024/128, QLEN/128), 256, GEMM_SMEM_BYTES>>>(hidh, hidl, wqf, pq, 1024, HID);
    kvproj_f2<<<dim3(512/128, QLEN/128, 4), 256, GEMM_SMEM_BYTES>>>(pk);

    norm_rope<<<8192, 256>>>(cosb, sinb, qw, kw);

    cudaFuncSetAttribute(attn_kernel, cudaFuncAttributeMaxDynamicSharedMemorySize, ATTN_SMEM_BYTES);
    attn_kernel<<<dim3(32, 16, NSPLIT), 256, ATTN_SMEM_BYTES>>>(mask, tb, rm);
    attn_combine<<<(QLEN*NHEADS*32 + 255)/256, 256>>>();

    gemm_f2<<<dim3(1024/128, QLEN/128), 256, GEMM_SMEM_BYTES>>>(aoh, aol, wof, out, 1024, HID);
}

// round 15
// speedup vs baseline: 1.5042x; 1.5042x over previous
#include <cuda_runtime.h>
#include <cuda_bf16.h>
#include <cuda_fp16.h>
#include <math.h>
#include <stdint.h>

#define NHEADS 16
#define NKVH   8
#define HDIM   64
#define QLEN   2048
#define CTXLEN 2048
#define TOT    4096
#define HID    1024
#define NSPLIT 4
#define SPLIT_KT 16

// fp32 intermediates
static __device__ float g_q [QLEN * NHEADS * HDIM];
static __device__ float g_k [TOT  * NKVH   * HDIM];

// attention split-K partials
static __device__ float g_po[NSPLIT][QLEN * NHEADS * HDIM];
static __device__ float g_pl[NSPLIT][QLEN * NHEADS];
static __device__ float g_pm[NSPLIT][QLEN * NHEADS];

// fp16 operand buffers
static __device__ __half c_hid_h[QLEN*HID], c_hid_l[QLEN*HID];
static __device__ __half c_tgt_h[CTXLEN*HID], c_tgt_l[CTXLEN*HID];
static __device__ __half c_wq_f [HID*1024];
static __device__ __half c_wk_f [HID*512];
static __device__ __half c_wv_f [HID*512];
static __device__ __half c_wo_f [1024*HID];
static __device__ __half c_ao_h [QLEN*1024], c_ao_l[QLEN*1024];

// attention operands: Q fp16 single, K fp16, V fp16
static __device__ __half c_q_f [QLEN*1024];
static __device__ __half c_k_f [TOT*512];
static __device__ __half c_v_f [TOT*512];

// ---------------- helpers ----------------
__device__ __forceinline__ uint32_t s2u(const void* p) {
    return (uint32_t)__cvta_generic_to_shared(p);
}
#define LDM_X4(r0,r1,r2,r3,a) \
    asm volatile("ldmatrix.sync.aligned.m8n8.x4.shared.b16 {%0,%1,%2,%3},[%4];" \
                 : "=r"(r0),"=r"(r1),"=r"(r2),"=r"(r3) : "r"(a))
#define LDM_X4T(r0,r1,r2,r3,a) \
    asm volatile("ldmatrix.sync.aligned.m8n8.x4.trans.shared.b16 {%0,%1,%2,%3},[%4];" \
                 : "=r"(r0),"=r"(r1),"=r"(r2),"=r"(r3) : "r"(a))
#define MMA_F16(c,a,b) \
    asm volatile("mma.sync.aligned.m16n8k16.row.col.f32.f16.f16.f32 " \
                 "{%0,%1,%2,%3},{%4,%5,%6,%7},{%8,%9},{%0,%1,%2,%3};" \
                 : "+f"(c[0]),"+f"(c[1]),"+f"(c[2]),"+f"(c[3]) \
                 : "r"(a[0]),"r"(a[1]),"r"(a[2]),"r"(a[3]),"r"(b[0]),"r"(b[1]))
#define CP16(dst,src) \
    asm volatile("cp.async.cg.shared.global [%0],[%1],16;" :: "r"(dst),"l"(src))
#define CP_COMMIT() asm volatile("cp.async.commit_group;")
#define CP_WAIT1()  asm volatile("cp.async.wait_group 1;")
#define CP_WAIT0()  asm volatile("cp.async.wait_group 0;")

__device__ __forceinline__ void split2h(float a, float b, uint32_t& hi, uint32_t& lo) {
    __half ha = __float2half_rn(a), hb = __float2half_rn(b);
    __half la = __float2half_rn(a - __half2float(ha));
    __half lb = __float2half_rn(b - __half2float(hb));
    hi = (uint32_t)__half_as_ushort(ha) | ((uint32_t)__half_as_ushort(hb) << 16);
    lo = (uint32_t)__half_as_ushort(la) | ((uint32_t)__half_as_ushort(lb) << 16);
}
__device__ __forceinline__ uint32_t packh2(float a, float b) {
    __half2 h = __floats2half2_rn(a, b);
    return *(uint32_t*)&h;
}

// ---------------- fused activation convert: hidden + target -> hi/lo fp16 ----
__global__ void cvt_acts(const float* __restrict__ hid, const float* __restrict__ tgt) {
    int base = (blockIdx.x * blockDim.x + threadIdx.x) * 4;
    const int n1 = QLEN * HID;
    const float* src; __half *hi, *lo; int off;
    if (base < n1) { src = hid; hi = c_hid_h; lo = c_hid_l; off = base; }
    else {
        off = base - n1;
        if (off >= CTXLEN * HID) return;
        src = tgt; hi = c_tgt_h; lo = c_tgt_l;
    }
    float4 v = *(const float4*)(src + off);
    uint32_t h0, l0, h1, l1;
    split2h(v.x, v.y, h0, l0);
    split2h(v.z, v.w, h1, l1);
    *(uint2*)(hi + off) = make_uint2(h0, h1);
    *(uint2*)(lo + off) = make_uint2(l0, l1);
}

// ---------------- fused weight convert ----------------
__global__ void cvt_wts(const float* __restrict__ Wq, const float* __restrict__ Wk,
                        const float* __restrict__ Wv, const float* __restrict__ Wo) {
    int base = (blockIdx.x * blockDim.x + threadIdx.x) * 4;
    const int nq = HID*1024, nk = HID*512, nv = HID*512, no = 1024*HID;
    const float* src; __half* dst; int off;
    if      (base < nq)              { src = Wq; dst = c_wq_f; off = base; }
    else if (base < nq+nk)           { src = Wk; dst = c_wk_f; off = base - nq; }
    else if (base < nq+nk+nv)        { src = Wv; dst = c_wv_f; off = base - nq - nk; }
    else if (base < nq+nk+nv+no)     { src = Wo; dst = c_wo_f; off = base - nq - nk - nv; }
    else return;
    float4 v = *(const float4*)(src + off);
    *(uint2*)(dst + off) = make_uint2(packh2(v.x, v.y), packh2(v.z, v.w));
}

// ---------------- tensor-core GEMM: fp16 2-term, occ=2 ----------
#define ASTR 40
#define BSTR 136
#define STAGEH (2*128*ASTR + 32*BSTR)
#define GEMM_SMEM_BYTES (2 * STAGEH * 2)

__device__ __forceinline__ void gemm_body(
    const __half* __restrict__ Ahi, const __half* __restrict__ Alo,
    const __half* __restrict__ Bf,
    float* __restrict__ C, __half* __restrict__ Ch,
    int N, int K, int bm, int bn, __half* sm)
{
    int tid = threadIdx.x;
    int lane = tid & 31, warp = tid >> 5;
    int wm = warp >> 2, wn = warp & 3;
    int lr = lane >> 2, lc = lane & 3;

    auto AsH = [&](int s) { return sm + s*STAGEH; };
    auto AsL = [&](int s) { return sm + s*STAGEH + 128*ASTR; };
    auto BsF = [&](int s) { return sm + s*STAGEH + 2*128*ASTR; };

    int arow = tid >> 2, aseg = tid & 3;
    int brow = tid >> 3, bseg = tid & 7;

    auto load_stage = [&](int s, int k0) {
        __half *ah = AsH(s), *al = AsL(s), *bf = BsF(s);
        #pragma unroll
        for (int r = 0; r < 2; r++) {
            int m = arow + r * 64;
            size_t g = (size_t)(bm + m) * K + k0 + aseg * 8;
            CP16(s2u(ah + m*ASTR + aseg*8), Ahi + g);
            CP16(s2u(al + m*ASTR + aseg*8), Alo + g);
        }
        #pragma unroll
        for (int r = 0; r < 2; r++) {
            int seg = bseg + r * 8;
            size_t g = (size_t)(k0 + brow) * N + bn + seg * 8;
            CP16(s2u(bf + brow*BSTR + seg*8), Bf + g);
        }
        CP_COMMIT();
    };

    float acc[4][4][4] = {};
    int T = K / 32;
    load_stage(0, 0);

    for (int t = 0; t < T; t++) {
        if (t + 1 < T) { load_stage((t + 1) & 1, (t + 1) * 32); CP_WAIT1(); }
        else           { CP_WAIT0(); }
        __syncthreads();
        __half *ah_ = AsH(t & 1), *al_ = AsL(t & 1), *bf_ = BsF(t & 1);
        #pragma unroll
        for (int ks = 0; ks < 2; ks++) {
            int kb = ks * 16;
            uint32_t ah[4][4], al[4][4], bf[4][2];
            #pragma unroll
            for (int mf = 0; mf < 4; mf++) {
                int r = wm*64 + mf*16 + (lane & 15);
                int c = kb + (lane >> 4) * 8;
                LDM_X4(ah[mf][0], ah[mf][1], ah[mf][2], ah[mf][3], s2u(ah_ + r*ASTR + c));
                LDM_X4(al[mf][0], al[mf][1], al[mf][2], al[mf][3], s2u(al_ + r*ASTR + c));
            }
            #pragma unroll
            for (int nfp = 0; nfp < 2; nfp++) {
                int r = kb + (lane & 7) + 8 * ((lane >> 3) & 1);
                int c = wn*32 + nfp*16 + (lane >> 4) * 8;
                LDM_X4T(bf[nfp*2][0], bf[nfp*2][1], bf[nfp*2+1][0], bf[nfp*2+1][1],
                        s2u(bf_ + r*BSTR + c));
            }
            #pragma unroll
            for (int mf = 0; mf < 4; mf++)
                #pragma unroll
                for (int nf = 0; nf < 4; nf++) {
                    MMA_F16(acc[mf][nf], al[mf], bf[nf]);
                    MMA_F16(acc[mf][nf], ah[mf], bf[nf]);
                }
        }
        __syncthreads();
    }
    if (Ch) {
        #pragma unroll
        for (int mf = 0; mf < 4; mf++) {
            int r0 = bm + wm*64 + mf*16 + lr;
            #pragma unroll
            for (int nf = 0; nf < 4; nf++) {
                int c0 = bn + wn*32 + nf*8 + 2*lc;
                *(uint32_t*)&Ch[(size_t)r0 * N + c0]       = packh2(acc[mf][nf][0], acc[mf][nf][1]);
                *(uint32_t*)&Ch[(size_t)(r0 + 8) * N + c0] = packh2(acc[mf][nf][2], acc[mf][nf][3]);
            }
        }
    } else {
        #pragma unroll
        for (int mf = 0; mf < 4; mf++) {
            int r0 = bm + wm*64 + mf*16 + lr;
            #pragma unroll
            for (int nf = 0; nf < 4; nf++) {
                int c0 = bn + wn*32 + nf*8 + 2*lc;
                *(float2*)&C[(size_t)r0 * N + c0]       = make_float2(acc[mf][nf][0], acc[mf][nf][1]);
                *(float2*)&C[(size_t)(r0 + 8) * N + c0] = make_float2(acc[mf][nf][2], acc[mf][nf][3]);
            }
        }
    }
}

__global__ __launch_bounds__(256, 2)
void gemm_f2(const __half* Ahi, const __half* Alo, const __half* Bf,
             float* C, int N, int K) {
    extern __shared__ __half gsm[];
    gemm_body(Ahi, Alo, Bf, C, nullptr, N, K, blockIdx.y * 128, blockIdx.x * 128, gsm);
}

// z = 0: Kctx(fp32), 1: Knoise(fp32), 2: Vctx(fp16 direct), 3: Vnoise(fp16 direct)
__global__ __launch_bounds__(256, 2)
void kvproj_f2(float* __restrict__ Kout) {
    extern __shared__ __half gsm[];
    int z = blockIdx.z;
    const __half *Ah = (z & 1) ? c_hid_h : c_tgt_h;
    const __half *Al = (z & 1) ? c_hid_l : c_tgt_l;
    const __half *Bf = (z < 2) ? c_wk_f : c_wv_f;
    size_t off = (z & 1) ? (size_t)QLEN * 512 : 0;
    float*  C  = (z < 2) ? Kout + off : nullptr;
    __half* Ch = (z < 2) ? nullptr : c_v_f + off;
    gemm_body(Ah, Al, Bf, C, Ch, 512, HID, blockIdx.y * 128, blockIdx.x * 128, gsm);
}

// ---------------- RMS-norm + RoPE: q,k -> single fp16 ----------
__global__ void norm_rope(const float* __restrict__ cosb, const float* __restrict__ sinb,
                          const float* __restrict__ qw,   const float* __restrict__ kw) {
    int warp = (blockIdx.x * blockDim.x + threadIdx.x) >> 5;
    int lane = threadIdx.x & 31;
    const float* src; size_t off; int pos; const float* w; bool isq;
    if (warp < QLEN * NHEADS) {
        int row = warp / NHEADS, h = warp % NHEADS;
        off = (size_t)row * 1024 + h * HDIM;
        src = g_q + off; pos = CTXLEN + row; w = qw; isq = true;
    } else {
        int v2 = warp - QLEN * NHEADS;
        int row = v2 / NKVH, h = v2 % NKVH;
        off = (size_t)row * 512 + h * HDIM;
        src = g_k + off; pos = row; w = kw; isq = false;
    }
    float x0 = src[lane], x1 = src[lane + 32];
    float ss = x0*x0 + x1*x1;
    #pragma unroll
    for (int o = 16; o; o >>= 1) ss += __shfl_xor_sync(0xffffffffu, ss, o);
    float r = rsqrtf(ss * (1.0f/64.0f) + 1e-6f);
    x0 *= r * w[lane];
    x1 *= r * w[lane + 32];
    float c0 = cosb[(size_t)pos*HDIM + lane], c1 = cosb[(size_t)pos*HDIM + lane + 32];
    float s0 = sinb[(size_t)pos*HDIM + lane], s1 = sinb[(size_t)pos*HDIM + lane + 32];
    float y0 = x0 * c0 - x1 * s0;
    float y1 = x1 * c1 + x0 * s1;
    __half* dst = isq ? c_q_f : c_k_f;
    dst[off + lane]      = __float2half_rn(y0);
    dst[off + lane + 32] = __float2half_rn(y1);
}

// ---------------- flash attention: fp16 QK 1-term, PV 1-term, split-K x4 ------
#define PADH 72
#define Q_BYTES   (4608*2)
#define WORK_OFF  Q_BYTES
#define WORK_BYTES 69632
#define STATS_OFF (WORK_OFF + WORK_BYTES)
#define ATTN_SMEM_BYTES (STATS_OFF + 2048)

__global__ __launch_bounds__(256, 2)
void attn_kernel(const float* __restrict__ mask,
                 const float* __restrict__ tree_bias,
                 const int*   __restrict__ relmap) {
    extern __shared__ char asmem[];
    __half* Qf = (__half*)asmem;
    __half* stg = (__half*)(asmem + WORK_OFF);
    float* red   = (float*)(asmem + WORK_OFF);
    float* mpart = (float*)(asmem + STATS_OFF);
    float* lpart = mpart + 256;

    int qb = blockIdx.x, h = blockIdx.y, sp = blockIdx.z;
    int kt0 = sp * SPLIT_KT;
    int kvh = h >> 1;
    int tid = threadIdx.x;
    int lane = tid & 31, warp = tid >> 5;
    int wm = warp >> 2, wn = warp & 3;
    int lr = lane >> 2, lc = lane & 3;

    {
        int row = tid >> 2;
        #pragma unroll
        for (int i = 0; i < 2; i++) {
            int seg = (tid & 3) + 4 * i;
            size_t g = (size_t)(qb*64 + row) * 1024 + h * HDIM + seg * 8;
            *(uint4*)&Qf[row*PADH + seg*8] = *(const uint4*)&c_q_f[g];
        }
    }

    int krow = tid >> 3, kseg = tid & 7;
    auto load_kv = [&](int s, int kt) {
        __half* Kf = stg + s*2*4608;
        __half* Vf = Kf + 4608;
        #pragma unroll
        for (int i = 0; i < 2; i++) {
            int kk = krow + 32*i;
            size_t g = (size_t)(kt*64 + kk) * 512 + kvh*HDIM + kseg*8;
            CP16(s2u(Kf + kk*PADH + kseg*8), c_k_f + g);
            CP16(s2u(Vf + kk*PADH + kseg*8), c_v_f + g);
        }
        CP_COMMIT();
    };

    float oacc[2][8][4] = {};
    float lacc[2][2] = {};
    float mrow[2][2] = {{-1e30f,-1e30f},{-1e30f,-1e30f}};

    load_kv(0, kt0);
    __syncthreads();

    for (int it = 0; it < SPLIT_KT; it++) {
        int kt = kt0 + it;
        CP_WAIT0();
        __syncthreads();
        if (it + 1 < SPLIT_KT) load_kv((it + 1) & 1, kt + 1);

        __half* Kf = stg + (it & 1)*2*4608;
        __half* Vf = Kf + 4608;

        // ---- S = Q @ K^T (single fp16 term) ----
        float s[2][2][4] = {};
        #pragma unroll
        for (int ks = 0; ks < 4; ks++) {
            int kb = ks * 16;
            uint32_t aq[2][4], bf[2][2];
            #pragma unroll
            for (int mf = 0; mf < 2; mf++) {
                int r = wm*32 + mf*16 + (lane & 15);
                int c = kb + (lane >> 4) * 8;
                LDM_X4(aq[mf][0], aq[mf][1], aq[mf][2], aq[mf][3], s2u(Qf + r*PADH + c));
            }
            {
                int r = wn*16 + (lane & 7) + 8 * (lane >> 4);
                int c = kb + 8 * ((lane >> 3) & 1);
                LDM_X4(bf[0][0], bf[0][1], bf[1][0], bf[1][1], s2u(Kf + r*PADH + c));
            }
            #pragma unroll
            for (int mf = 0; mf < 2; mf++)
                #pragma unroll
                for (int nf = 0; nf < 2; nf++)
                    MMA_F16(s[mf][nf], aq[mf], bf[nf]);
        }

        // ---- scale + mask + bias; warp-local online softmax ----
        int qg = qb * 64, kg = kt * 64;
        bool diag = (kt == 32 + qb);
        uint32_t pa[2][4];
        #pragma unroll
        for (int mf = 0; mf < 2; mf++) {
            int r0 = wm*32 + mf*16 + lr;
            #pragma unroll
            for (int nf = 0; nf < 2; nf++) {
                int c0 = wn*16 + nf*8 + 2*lc;
                float2 m0 = *(const float2*)&mask[(size_t)(qg + r0)     * TOT + kg + c0];
                float2 m1 = *(const float2*)&mask[(size_t)(qg + r0 + 8) * TOT + kg + c0];
                s[mf][nf][0] = s[mf][nf][0]*0.125f + m0.x;
                s[mf][nf][1] = s[mf][nf][1]*0.125f + m0.y;
                s[mf][nf][2] = s[mf][nf][2]*0.125f + m1.x;
                s[mf][nf][3] = s[mf][nf][3]*0.125f + m1.y;
                if (diag) {
                    s[mf][nf][0] += tree_bias[relmap[qb*4096 +  r0     *64 + c0    ] * NHEADS + h];
                    s[mf][nf][1] += tree_bias[relmap[qb*4096 +  r0     *64 + c0 + 1] * NHEADS + h];
                    s[mf][nf][2] += tree_bias[relmap[qb*4096 + (r0 + 8)*64 + c0    ] * NHEADS + h];
                    s[mf][nf][3] += tree_bias[relmap[qb*4096 + (r0 + 8)*64 + c0 + 1] * NHEADS + h];
                }
            }
            float mx0 = fmaxf(fmaxf(s[mf][0][0], s[mf][0][1]), fmaxf(s[mf][1][0], s[mf][1][1]));
            float mx1 = fmaxf(fmaxf(s[mf][0][2], s[mf][0][3]), fmaxf(s[mf][1][2], s[mf][1][3]));
            mx0 = fmaxf(mx0, __shfl_xor_sync(0xffffffffu, mx0, 1));
            mx0 = fmaxf(mx0, __shfl_xor_sync(0xffffffffu, mx0, 2));
            mx1 = fmaxf(mx1, __shfl_xor_sync(0xffffffffu, mx1, 1));
            mx1 = fmaxf(mx1, __shfl_xor_sync(0xffffffffu, mx1, 2));
            mx0 = fmaxf(mx0, mrow[mf][0]);
            mx1 = fmaxf(mx1, mrow[mf][1]);
            float sc0 = __expf(mrow[mf][0] - mx0);
            float sc1 = __expf(mrow[mf][1] - mx1);
            mrow[mf][0] = mx0; mrow[mf][1] = mx1;
            float p[2][4];
            #pragma unroll
            for (int nf = 0; nf < 2; nf++) {
                p[nf][0] = __expf(s[mf][nf][0] - mx0);
                p[nf][1] = __expf(s[mf][nf][1] - mx0);
                p[nf][2] = __expf(s[mf][nf][2] - mx1);
                p[nf][3] = __expf(s[mf][nf][3] - mx1);
            }
            lacc[mf][0] = lacc[mf][0]*sc0 + p[0][0]+p[0][1]+p[1][0]+p[1][1];
            lacc[mf][1] = lacc[mf][1]*sc1 + p[0][2]+p[0][3]+p[1][2]+p[1][3];
            #pragma unroll
            for (int nf = 0; nf < 8; nf++) {
                oacc[mf][nf][0] *= sc0; oacc[mf][nf][1] *= sc0;
                oacc[mf][nf][2] *= sc1; oacc[mf][nf][3] *= sc1;
            }
            pa[mf][0] = packh2(p[0][0], p[0][1]);
            pa[mf][1] = packh2(p[0][2], p[0][3]);
            pa[mf][2] = packh2(p[1][0], p[1][1]);
            pa[mf][3] = packh2(p[1][2], p[1][3]);
        }

        // ---- O += P @ V ----
        #pragma unroll
        for (int ng = 0; ng < 4; ng++) {
            uint32_t bv[2][2];
            int r = wn*16 + (lane & 7) + 8 * ((lane >> 3) & 1);
            int c = ng*16 + (lane >> 4) * 8;
            LDM_X4T(bv[0][0], bv[0][1], bv[1][0], bv[1][1], s2u(Vf + r*PADH + c));
            #pragma unroll
            for (int mf = 0; mf < 2; mf++)
                #pragma unroll
                for (int j = 0; j < 2; j++)
                    MMA_F16(oacc[mf][ng*2+j], pa[mf], bv[j]);
        }
    }

    // ---- cross-warp combine ----
    __syncthreads();
    #pragma unroll
    for (int mf = 0; mf < 2; mf++) {
        float l0 = lacc[mf][0], l1 = lacc[mf][1];
        l0 += __shfl_xor_sync(0xffffffffu, l0, 1);
        l0 += __shfl_xor_sync(0xffffffffu, l0, 2);
        l1 += __shfl_xor_sync(0xffffffffu, l1, 1);
        l1 += __shfl_xor_sync(0xffffffffu, l1, 2);
        if (lc == 0) {
            lpart[(wm*32 + mf*16 + lr    )*4 + wn] = l0;
            lpart[(wm*32 + mf*16 + lr + 8)*4 + wn] = l1;
            mpart[(wm*32 + mf*16 + lr    )*4 + wn] = mrow[mf][0];
            mpart[(wm*32 + mf*16 + lr + 8)*4 + wn] = mrow[mf][1];
        }
    }
    #pragma unroll
    for (int mf = 0; mf < 2; mf++) {
        int r0 = wm*32 + mf*16 + lr;
        #pragma unroll
        for (int nf = 0; nf < 8; nf++) {
            int c0 = nf*8 + 2*lc;
            *(float2*)&red[((size_t)wn*64 + r0    )*68 + c0] = make_float2(oacc[mf][nf][0], oacc[mf][nf][1]);
            *(float2*)&red[((size_t)wn*64 + r0 + 8)*68 + c0] = make_float2(oacc[mf][nf][2], oacc[mf][nf][3]);
        }
    }
    __syncthreads();

    {
        int row = tid >> 2, db = (tid & 3) * 16;
        float4 mp = *(float4*)&mpart[row*4];
        float M = fmaxf(fmaxf(mp.x, mp.y), fmaxf(mp.z, mp.w));
        float w0 = __expf(mp.x - M), w1 = __expf(mp.y - M);
        float w2 = __expf(mp.z - M), w3 = __expf(mp.w - M);
        float4 lp = *(float4*)&lpart[row*4];
        float lsum = w0*lp.x + w1*lp.y + w2*lp.z + w3*lp.w;
        size_t gbase = (size_t)(qb*64 + row) * 1024 + h*HDIM + db;
        #pragma unroll
        for (int j = 0; j < 4; j++) {
            int d = db + j*4;
            float4 a0 = *(float4*)&red[((size_t)0*64 + row)*68 + d];
            float4 a1 = *(float4*)&red[((size_t)1*64 + row)*68 + d];
            float4 a2 = *(float4*)&red[((size_t)2*64 + row)*68 + d];
            float4 a3 = *(float4*)&red[((size_t)3*64 + row)*68 + d];
            *(float4*)&g_po[sp][gbase + j*4] = make_float4(
                w0*a0.x + w1*a1.x + w2*a2.x + w3*a3.x,
                w0*a0.y + w1*a1.y + w2*a2.y + w3*a3.y,
                w0*a0.z + w1*a1.z + w2*a2.z + w3*a3.z,
                w0*a0.w + w1*a1.w + w2*a2.w + w3*a3.w);
        }
        if ((tid & 3) == 0) {
            g_pl[sp][(qb*64 + row)*16 + h] = lsum;
            g_pm[sp][(qb*64 + row)*16 + h] = M;
        }
    }
}

// ---------------- split-K combine (4 partials) -> c_ao fp16 hi/lo ----------------
__global__ void attn_combine() {
    int gw = (blockIdx.x * blockDim.x + threadIdx.x) >> 5;
    int lane = threadIdx.x & 31;
    if (gw >= QLEN * NHEADS) return;
    int row = gw >> 4, h = gw & 15;
    int il = row * 16 + h;
    float m0 = g_pm[0][il], m1 = g_pm[1][il], m2 = g_pm[2][il], m3 = g_pm[3][il];
    float M = fmaxf(fmaxf(m0, m1), fmaxf(m2, m3));
    float w0 = __expf(m0 - M), w1 = __expf(m1 - M);
    float w2 = __expf(m2 - M), w3 = __expf(m3 - M);
    float l = w0*g_pl[0][il] + w1*g_pl[1][il] + w2*g_pl[2][il] + w3*g_pl[3][il];
    float inv = 1.0f / l;
    size_t base = (size_t)row * 1024 + h * HDIM;
    float2 a0 = *(float2*)&g_po[0][base + 2*lane];
    float2 a1 = *(float2*)&g_po[1][base + 2*lane];
    float2 a2 = *(float2*)&g_po[2][base + 2*lane];
    float2 a3 = *(float2*)&g_po[3][base + 2*lane];
    float v0 = (w0*a0.x + w1*a1.x + w2*a2.x + w3*a3.x) * inv;
    float v1 = (w0*a0.y + w1*a1.y + w2*a2.y + w3*a3.y) * inv;
    uint32_t hi, lo;
    split2h(v0, v1, hi, lo);
    *(uint32_t*)&c_ao_h[base + 2*lane] = hi;
    *(uint32_t*)&c_ao_l[base + 2*lane] = lo;
}

// ---------------------------------------------------------------------------
extern "C" void kernel_launch(void* const* d_in, const int* in_sizes, int n_in,
                              void* d_out, int out_size) {
    const float* hidden = (const float*)d_in[0];
    const float* target = (const float*)d_in[1];
    const float* cosb   = (const float*)d_in[2];
    const float* sinb   = (const float*)d_in[3];
    const float* mask   = (const float*)d_in[4];
    const float* Wq     = (const float*)d_in[5];
    const float* Wk     = (const float*)d_in[6];
    const float* Wv     = (const float*)d_in[7];
    const float* Wo     = (const float*)d_in[8];
    const float* qw     = (const float*)d_in[9];
    const float* kw     = (const float*)d_in[10];
    const float* tb     = (const float*)d_in[11];
    const int*   rm     = (const int*)d_in[12];
    float* out = (float*)d_out;

    float *pq, *pk;
    cudaGetSymbolAddress((void**)&pq, g_q);
    cudaGetSymbolAddress((void**)&pk, g_k);

    __half *hidh,*hidl,*wqf,*wof,*aoh,*aol;
    cudaGetSymbolAddress((void**)&hidh, c_hid_h); cudaGetSymbolAddress((void**)&hidl, c_hid_l);
    cudaGetSymbolAddress((void**)&wqf,  c_wq_f);
    cudaGetSymbolAddress((void**)&wof,  c_wo_f);
    cudaGetSymbolAddress((void**)&aoh,  c_ao_h);  cudaGetSymbolAddress((void**)&aol,  c_ao_l);

    cvt_acts<<<((QLEN+CTXLEN)*HID/4 + 255)/256, 256>>>(hidden, target);
    cvt_wts<<<((HID*1024 + HID*512 + HID*512 + 1024*HID)/4 + 255)/256, 256>>>(Wq, Wk, Wv, Wo);

    cudaFuncSetAttribute(gemm_f2,   cudaFuncAttributeMaxDynamicSharedMemorySize, GEMM_SMEM_BYTES);
    cudaFuncSetAttribute(kvproj_f2, cudaFuncAttributeMaxDynamicSharedMemorySize, GEMM_SMEM_BYTES);

    gemm_f2<<<dim3(1024/128, QLEN/128), 256, GEMM_SMEM_BYTES>>>(hidh, hidl, wqf, pq, 1024, HID);
    kvproj_f2<<<dim3(512/128, QLEN/128, 4), 256, GEMM_SMEM_BYTES>>>(pk);

    norm_rope<<<8192, 256>>>(cosb, sinb, qw, kw);

    cudaFuncSetAttribute(attn_kernel, cudaFuncAttributeMaxDynamicSharedMemorySize, ATTN_SMEM_BYTES);
    attn_kernel<<<dim3(32, 16, NSPLIT), 256, ATTN_SMEM_BYTES>>>(mask, tb, rm);
    attn_combine<<<(QLEN*NHEADS*32 + 255)/256, 256>>>();

    gemm_f2<<<dim3(1024/128, QLEN/128), 256, GEMM_SMEM_BYTES>>>(aoh, aol, wof, out, 1024, HID);
}

// round 16
// speedup vs baseline: 1.7151x; 1.1402x over previous
#include <cuda_runtime.h>
#include <cuda_bf16.h>
#include <cuda_fp16.h>
#include <math.h>
#include <stdint.h>

#define NHEADS 16
#define NKVH   8
#define HDIM   64
#define QLEN   2048
#define CTXLEN 2048
#define TOT    4096
#define HID    1024
#define NSPLIT 4
#define SPLIT_KT 16

// fp32 intermediates
static __device__ float g_q [QLEN * NHEADS * HDIM];
static __device__ float g_k [TOT  * NKVH   * HDIM];

// attention split-K partials
static __device__ float g_po[NSPLIT][QLEN * NHEADS * HDIM];
static __device__ float g_pl[NSPLIT][QLEN * NHEADS];
static __device__ float g_pm[NSPLIT][QLEN * NHEADS];

// fp16 operand buffers (all single precision fp16 now)
static __device__ __half c_hid_f[QLEN*HID];
static __device__ __half c_tgt_f[CTXLEN*HID];
static __device__ __half c_wq_f [HID*1024];
static __device__ __half c_wk_f [HID*512];
static __device__ __half c_wv_f [HID*512];
static __device__ __half c_wo_f [1024*HID];
static __device__ __half c_ao_f [QLEN*1024];

// attention operands
static __device__ __half c_q_f [QLEN*1024];
static __device__ __half c_k_f [TOT*512];
static __device__ __half c_v_f [TOT*512];

// ---------------- helpers ----------------
__device__ __forceinline__ uint32_t s2u(const void* p) {
    return (uint32_t)__cvta_generic_to_shared(p);
}
#define LDM_X4(r0,r1,r2,r3,a) \
    asm volatile("ldmatrix.sync.aligned.m8n8.x4.shared.b16 {%0,%1,%2,%3},[%4];" \
                 : "=r"(r0),"=r"(r1),"=r"(r2),"=r"(r3) : "r"(a))
#define LDM_X4T(r0,r1,r2,r3,a) \
    asm volatile("ldmatrix.sync.aligned.m8n8.x4.trans.shared.b16 {%0,%1,%2,%3},[%4];" \
                 : "=r"(r0),"=r"(r1),"=r"(r2),"=r"(r3) : "r"(a))
#define MMA_F16(c,a,b) \
    asm volatile("mma.sync.aligned.m16n8k16.row.col.f32.f16.f16.f32 " \
                 "{%0,%1,%2,%3},{%4,%5,%6,%7},{%8,%9},{%0,%1,%2,%3};" \
                 : "+f"(c[0]),"+f"(c[1]),"+f"(c[2]),"+f"(c[3]) \
                 : "r"(a[0]),"r"(a[1]),"r"(a[2]),"r"(a[3]),"r"(b[0]),"r"(b[1]))
#define CP16(dst,src) \
    asm volatile("cp.async.cg.shared.global [%0],[%1],16;" :: "r"(dst),"l"(src))
#define CP_COMMIT() asm volatile("cp.async.commit_group;")
#define CP_WAIT1()  asm volatile("cp.async.wait_group 1;")
#define CP_WAIT0()  asm volatile("cp.async.wait_group 0;")

__device__ __forceinline__ uint32_t packh2(float a, float b) {
    __half2 h = __floats2half2_rn(a, b);
    return *(uint32_t*)&h;
}

// ---------------- fused activation convert: hidden + target -> fp16 ----
__global__ void cvt_acts(const float* __restrict__ hid, const float* __restrict__ tgt) {
    int base = (blockIdx.x * blockDim.x + threadIdx.x) * 4;
    const int n1 = QLEN * HID;
    const float* src; __half* dst; int off;
    if (base < n1) { src = hid; dst = c_hid_f; off = base; }
    else {
        off = base - n1;
        if (off >= CTXLEN * HID) return;
        src = tgt; dst = c_tgt_f;
    }
    float4 v = *(const float4*)(src + off);
    *(uint2*)(dst + off) = make_uint2(packh2(v.x, v.y), packh2(v.z, v.w));
}

// ---------------- fused weight convert ----------------
__global__ void cvt_wts(const float* __restrict__ Wq, const float* __restrict__ Wk,
                        const float* __restrict__ Wv, const float* __restrict__ Wo) {
    int base = (blockIdx.x * blockDim.x + threadIdx.x) * 4;
    const int nq = HID*1024, nk = HID*512, nv = HID*512, no = 1024*HID;
    const float* src; __half* dst; int off;
    if      (base < nq)              { src = Wq; dst = c_wq_f; off = base; }
    else if (base < nq+nk)           { src = Wk; dst = c_wk_f; off = base - nq; }
    else if (base < nq+nk+nv)        { src = Wv; dst = c_wv_f; off = base - nq - nk; }
    else if (base < nq+nk+nv+no)     { src = Wo; dst = c_wo_f; off = base - nq - nk - nv; }
    else return;
    float4 v = *(const float4*)(src + off);
    *(uint2*)(dst + off) = make_uint2(packh2(v.x, v.y), packh2(v.z, v.w));
}

// ---------------- tensor-core GEMM: fp16 1-term (A single, B single), occ=2 ----
#define ASTR 40
#define BSTR 136
#define STAGEH (128*ASTR + 32*BSTR)
#define GEMM_SMEM_BYTES (2 * STAGEH * 2)

__device__ __forceinline__ void gemm_body(
    const __half* __restrict__ Af, const __half* __restrict__ Bf,
    float* __restrict__ C, __half* __restrict__ Ch,
    int N, int K, int bm, int bn, __half* sm)
{
    int tid = threadIdx.x;
    int lane = tid & 31, warp = tid >> 5;
    int wm = warp >> 2, wn = warp & 3;
    int lr = lane >> 2, lc = lane & 3;

    auto AsF = [&](int s) { return sm + s*STAGEH; };
    auto BsF = [&](int s) { return sm + s*STAGEH + 128*ASTR; };

    int arow = tid >> 2, aseg = tid & 3;
    int brow = tid >> 3, bseg = tid & 7;

    auto load_stage = [&](int s, int k0) {
        __half *af = AsF(s), *bf = BsF(s);
        #pragma unroll
        for (int r = 0; r < 2; r++) {
            int m = arow + r * 64;
            size_t g = (size_t)(bm + m) * K + k0 + aseg * 8;
            CP16(s2u(af + m*ASTR + aseg*8), Af + g);
        }
        #pragma unroll
        for (int r = 0; r < 2; r++) {
            int seg = bseg + r * 8;
            size_t g = (size_t)(k0 + brow) * N + bn + seg * 8;
            CP16(s2u(bf + brow*BSTR + seg*8), Bf + g);
        }
        CP_COMMIT();
    };

    float acc[4][4][4] = {};
    int T = K / 32;
    load_stage(0, 0);

    for (int t = 0; t < T; t++) {
        if (t + 1 < T) { load_stage((t + 1) & 1, (t + 1) * 32); CP_WAIT1(); }
        else           { CP_WAIT0(); }
        __syncthreads();
        __half *af_ = AsF(t & 1), *bf_ = BsF(t & 1);
        #pragma unroll
        for (int ks = 0; ks < 2; ks++) {
            int kb = ks * 16;
            uint32_t af[4][4], bf[4][2];
            #pragma unroll
            for (int mf = 0; mf < 4; mf++) {
                int r = wm*64 + mf*16 + (lane & 15);
                int c = kb + (lane >> 4) * 8;
                LDM_X4(af[mf][0], af[mf][1], af[mf][2], af[mf][3], s2u(af_ + r*ASTR + c));
            }
            #pragma unroll
            for (int nfp = 0; nfp < 2; nfp++) {
                int r = kb + (lane & 7) + 8 * ((lane >> 3) & 1);
                int c = wn*32 + nfp*16 + (lane >> 4) * 8;
                LDM_X4T(bf[nfp*2][0], bf[nfp*2][1], bf[nfp*2+1][0], bf[nfp*2+1][1],
                        s2u(bf_ + r*BSTR + c));
            }
            #pragma unroll
            for (int mf = 0; mf < 4; mf++)
                #pragma unroll
                for (int nf = 0; nf < 4; nf++)
                    MMA_F16(acc[mf][nf], af[mf], bf[nf]);
        }
        __syncthreads();
    }
    if (Ch) {
        #pragma unroll
        for (int mf = 0; mf < 4; mf++) {
            int r0 = bm + wm*64 + mf*16 + lr;
            #pragma unroll
            for (int nf = 0; nf < 4; nf++) {
                int c0 = bn + wn*32 + nf*8 + 2*lc;
                *(uint32_t*)&Ch[(size_t)r0 * N + c0]       = packh2(acc[mf][nf][0], acc[mf][nf][1]);
                *(uint32_t*)&Ch[(size_t)(r0 + 8) * N + c0] = packh2(acc[mf][nf][2], acc[mf][nf][3]);
            }
        }
    } else {
        #pragma unroll
        for (int mf = 0; mf < 4; mf++) {
            int r0 = bm + wm*64 + mf*16 + lr;
            #pragma unroll
            for (int nf = 0; nf < 4; nf++) {
                int c0 = bn + wn*32 + nf*8 + 2*lc;
                *(float2*)&C[(size_t)r0 * N + c0]       = make_float2(acc[mf][nf][0], acc[mf][nf][1]);
                *(float2*)&C[(size_t)(r0 + 8) * N + c0] = make_float2(acc[mf][nf][2], acc[mf][nf][3]);
            }
        }
    }
}

__global__ __launch_bounds__(256, 2)
void gemm_f1(const __half* Af, const __half* Bf, float* C, int N, int K) {
    extern __shared__ __half gsm[];
    gemm_body(Af, Bf, C, nullptr, N, K, blockIdx.y * 128, blockIdx.x * 128, gsm);
}

// z = 0: Kctx(fp32), 1: Knoise(fp32), 2: Vctx(fp16 direct), 3: Vnoise(fp16 direct)
__global__ __launch_bounds__(256, 2)
void kvproj_f1(float* __restrict__ Kout) {
    extern __shared__ __half gsm[];
    int z = blockIdx.z;
    const __half *Af = (z & 1) ? c_hid_f : c_tgt_f;
    const __half *Bf = (z < 2) ? c_wk_f : c_wv_f;
    size_t off = (z & 1) ? (size_t)QLEN * 512 : 0;
    float*  C  = (z < 2) ? Kout + off : nullptr;
    __half* Ch = (z < 2) ? nullptr : c_v_f + off;
    gemm_body(Af, Bf, C, Ch, 512, HID, blockIdx.y * 128, blockIdx.x * 128, gsm);
}

// ---------------- RMS-norm + RoPE: q,k -> single fp16 ----------
__global__ void norm_rope(const float* __restrict__ cosb, const float* __restrict__ sinb,
                          const float* __restrict__ qw,   const float* __restrict__ kw) {
    int warp = (blockIdx.x * blockDim.x + threadIdx.x) >> 5;
    int lane = threadIdx.x & 31;
    const float* src; size_t off; int pos; const float* w; bool isq;
    if (warp < QLEN * NHEADS) {
        int row = warp / NHEADS, h = warp % NHEADS;
        off = (size_t)row * 1024 + h * HDIM;
        src = g_q + off; pos = CTXLEN + row; w = qw; isq = true;
    } else {
        int v2 = warp - QLEN * NHEADS;
        int row = v2 / NKVH, h = v2 % NKVH;
        off = (size_t)row * 512 + h * HDIM;
        src = g_k + off; pos = row; w = kw; isq = false;
    }
    float x0 = src[lane], x1 = src[lane + 32];
    float ss = x0*x0 + x1*x1;
    #pragma unroll
    for (int o = 16; o; o >>= 1) ss += __shfl_xor_sync(0xffffffffu, ss, o);
    float r = rsqrtf(ss * (1.0f/64.0f) + 1e-6f);
    x0 *= r * w[lane];
    x1 *= r * w[lane + 32];
    float c0 = cosb[(size_t)pos*HDIM + lane], c1 = cosb[(size_t)pos*HDIM + lane + 32];
    float s0 = sinb[(size_t)pos*HDIM + lane], s1 = sinb[(size_t)pos*HDIM + lane + 32];
    float y0 = x0 * c0 - x1 * s0;
    float y1 = x1 * c1 + x0 * s1;
    __half* dst = isq ? c_q_f : c_k_f;
    dst[off + lane]      = __float2half_rn(y0);
    dst[off + lane + 32] = __float2half_rn(y1);
}

// ---------------- flash attention: fp16 QK 1-term, PV 1-term, split-K x4 ------
#define PADH 72
#define Q_BYTES   (4608*2)
#define WORK_OFF  Q_BYTES
#define WORK_BYTES 69632
#define STATS_OFF (WORK_OFF + WORK_BYTES)
#define ATTN_SMEM_BYTES (STATS_OFF + 2048)

__global__ __launch_bounds__(256, 2)
void attn_kernel(const float* __restrict__ mask,
                 const float* __restrict__ tree_bias,
                 const int*   __restrict__ relmap) {
    extern __shared__ char asmem[];
    __half* Qf = (__half*)asmem;
    __half* stg = (__half*)(asmem + WORK_OFF);
    float* red   = (float*)(asmem + WORK_OFF);
    float* mpart = (float*)(asmem + STATS_OFF);
    float* lpart = mpart + 256;

    int qb = blockIdx.x, h = blockIdx.y, sp = blockIdx.z;
    int kt0 = sp * SPLIT_KT;
    int kvh = h >> 1;
    int tid = threadIdx.x;
    int lane = tid & 31, warp = tid >> 5;
    int wm = warp >> 2, wn = warp & 3;
    int lr = lane >> 2, lc = lane & 3;

    {
        int row = tid >> 2;
        #pragma unroll
        for (int i = 0; i < 2; i++) {
            int seg = (tid & 3) + 4 * i;
            size_t g = (size_t)(qb*64 + row) * 1024 + h * HDIM + seg * 8;
            *(uint4*)&Qf[row*PADH + seg*8] = *(const uint4*)&c_q_f[g];
        }
    }

    int krow = tid >> 3, kseg = tid & 7;
    auto load_kv = [&](int s, int kt) {
        __half* Kf = stg + s*2*4608;
        __half* Vf = Kf + 4608;
        #pragma unroll
        for (int i = 0; i < 2; i++) {
            int kk = krow + 32*i;
            size_t g = (size_t)(kt*64 + kk) * 512 + kvh*HDIM + kseg*8;
            CP16(s2u(Kf + kk*PADH + kseg*8), c_k_f + g);
            CP16(s2u(Vf + kk*PADH + kseg*8), c_v_f + g);
        }
        CP_COMMIT();
    };

    float oacc[2][8][4] = {};
    float lacc[2][2] = {};
    float mrow[2][2] = {{-1e30f,-1e30f},{-1e30f,-1e30f}};

    load_kv(0, kt0);
    __syncthreads();

    for (int it = 0; it < SPLIT_KT; it++) {
        int kt = kt0 + it;
        CP_WAIT0();
        __syncthreads();
        if (it + 1 < SPLIT_KT) load_kv((it + 1) & 1, kt + 1);

        __half* Kf = stg + (it & 1)*2*4608;
        __half* Vf = Kf + 4608;

        // ---- S = Q @ K^T (single fp16 term) ----
        float s[2][2][4] = {};
        #pragma unroll
        for (int ks = 0; ks < 4; ks++) {
            int kb = ks * 16;
            uint32_t aq[2][4], bf[2][2];
            #pragma unroll
            for (int mf = 0; mf < 2; mf++) {
                int r = wm*32 + mf*16 + (lane & 15);
                int c = kb + (lane >> 4) * 8;
                LDM_X4(aq[mf][0], aq[mf][1], aq[mf][2], aq[mf][3], s2u(Qf + r*PADH + c));
            }
            {
                int r = wn*16 + (lane & 7) + 8 * (lane >> 4);
                int c = kb + 8 * ((lane >> 3) & 1);
                LDM_X4(bf[0][0], bf[0][1], bf[1][0], bf[1][1], s2u(Kf + r*PADH + c));
            }
            #pragma unroll
            for (int mf = 0; mf < 2; mf++)
                #pragma unroll
                for (int nf = 0; nf < 2; nf++)
                    MMA_F16(s[mf][nf], aq[mf], bf[nf]);
        }

        // ---- scale + mask + bias; warp-local online softmax ----
        int qg = qb * 64, kg = kt * 64;
        bool diag = (kt == 32 + qb);
        uint32_t pa[2][4];
        #pragma unroll
        for (int mf = 0; mf < 2; mf++) {
            int r0 = wm*32 + mf*16 + lr;
            #pragma unroll
            for (int nf = 0; nf < 2; nf++) {
                int c0 = wn*16 + nf*8 + 2*lc;
                float2 m0 = *(const float2*)&mask[(size_t)(qg + r0)     * TOT + kg + c0];
                float2 m1 = *(const float2*)&mask[(size_t)(qg + r0 + 8) * TOT + kg + c0];
                s[mf][nf][0] = s[mf][nf][0]*0.125f + m0.x;
                s[mf][nf][1] = s[mf][nf][1]*0.125f + m0.y;
                s[mf][nf][2] = s[mf][nf][2]*0.125f + m1.x;
                s[mf][nf][3] = s[mf][nf][3]*0.125f + m1.y;
                if (diag) {
                    s[mf][nf][0] += tree_bias[relmap[qb*4096 +  r0     *64 + c0    ] * NHEADS + h];
                    s[mf][nf][1] += tree_bias[relmap[qb*4096 +  r0     *64 + c0 + 1] * NHEADS + h];
                    s[mf][nf][2] += tree_bias[relmap[qb*4096 + (r0 + 8)*64 + c0    ] * NHEADS + h];
                    s[mf][nf][3] += tree_bias[relmap[qb*4096 + (r0 + 8)*64 + c0 + 1] * NHEADS + h];
                }
            }
            float mx0 = fmaxf(fmaxf(s[mf][0][0], s[mf][0][1]), fmaxf(s[mf][1][0], s[mf][1][1]));
            float mx1 = fmaxf(fmaxf(s[mf][0][2], s[mf][0][3]), fmaxf(s[mf][1][2], s[mf][1][3]));
            mx0 = fmaxf(mx0, __shfl_xor_sync(0xffffffffu, mx0, 1));
            mx0 = fmaxf(mx0, __shfl_xor_sync(0xffffffffu, mx0, 2));
            mx1 = fmaxf(mx1, __shfl_xor_sync(0xffffffffu, mx1, 1));
            mx1 = fmaxf(mx1, __shfl_xor_sync(0xffffffffu, mx1, 2));
            mx0 = fmaxf(mx0, mrow[mf][0]);
            mx1 = fmaxf(mx1, mrow[mf][1]);
            float sc0 = __expf(mrow[mf][0] - mx0);
            float sc1 = __expf(mrow[mf][1] - mx1);
            mrow[mf][0] = mx0; mrow[mf][1] = mx1;
            float p[2][4];
            #pragma unroll
            for (int nf = 0; nf < 2; nf++) {
                p[nf][0] = __expf(s[mf][nf][0] - mx0);
                p[nf][1] = __expf(s[mf][nf][1] - mx0);
                p[nf][2] = __expf(s[mf][nf][2] - mx1);
                p[nf][3] = __expf(s[mf][nf][3] - mx1);
            }
            lacc[mf][0] = lacc[mf][0]*sc0 + p[0][0]+p[0][1]+p[1][0]+p[1][1];
            lacc[mf][1] = lacc[mf][1]*sc1 + p[0][2]+p[0][3]+p[1][2]+p[1][3];
            #pragma unroll
            for (int nf = 0; nf < 8; nf++) {
                oacc[mf][nf][0] *= sc0; oacc[mf][nf][1] *= sc0;
                oacc[mf][nf][2] *= sc1; oacc[mf][nf][3] *= sc1;
            }
            pa[mf][0] = packh2(p[0][0], p[0][1]);
            pa[mf][1] = packh2(p[0][2], p[0][3]);
            pa[mf][2] = packh2(p[1][0], p[1][1]);
            pa[mf][3] = packh2(p[1][2], p[1][3]);
        }

        // ---- O += P @ V ----
        #pragma unroll
        for (int ng = 0; ng < 4; ng++) {
            uint32_t bv[2][2];
            int r = wn*16 + (lane & 7) + 8 * ((lane >> 3) & 1);
            int c = ng*16 + (lane >> 4) * 8;
            LDM_X4T(bv[0][0], bv[0][1], bv[1][0], bv[1][1], s2u(Vf + r*PADH + c));
            #pragma unroll
            for (int mf = 0; mf < 2; mf++)
                #pragma unroll
                for (int j = 0; j < 2; j++)
                    MMA_F16(oacc[mf][ng*2+j], pa[mf], bv[j]);
        }
    }

    // ---- cross-warp combine ----
    __syncthreads();
    #pragma unroll
    for (int mf = 0; mf < 2; mf++) {
        float l0 = lacc[mf][0], l1 = lacc[mf][1];
        l0 += __shfl_xor_sync(0xffffffffu, l0, 1);
        l0 += __shfl_xor_sync(0xffffffffu, l0, 2);
        l1 += __shfl_xor_sync(0xffffffffu, l1, 1);
        l1 += __shfl_xor_sync(0xffffffffu, l1, 2);
        if (lc == 0) {
            lpart[(wm*32 + mf*16 + lr    )*4 + wn] = l0;
            lpart[(wm*32 + mf*16 + lr + 8)*4 + wn] = l1;
            mpart[(wm*32 + mf*16 + lr    )*4 + wn] = mrow[mf][0];
            mpart[(wm*32 + mf*16 + lr + 8)*4 + wn] = mrow[mf][1];
        }
    }
    #pragma unroll
    for (int mf = 0; mf < 2; mf++) {
        int r0 = wm*32 + mf*16 + lr;
        #pragma unroll
        for (int nf = 0; nf < 8; nf++) {
            int c0 = nf*8 + 2*lc;
            *(float2*)&red[((size_t)wn*64 + r0    )*68 + c0] = make_float2(oacc[mf][nf][0], oacc[mf][nf][1]);
            *(float2*)&red[((size_t)wn*64 + r0 + 8)*68 + c0] = make_float2(oacc[mf][nf][2], oacc[mf][nf][3]);
        }
    }
    __syncthreads();

    {
        int row = tid >> 2, db = (tid & 3) * 16;
        float4 mp = *(float4*)&mpart[row*4];
        float M = fmaxf(fmaxf(mp.x, mp.y), fmaxf(mp.z, mp.w));
        float w0 = __expf(mp.x - M), w1 = __expf(mp.y - M);
        float w2 = __expf(mp.z - M), w3 = __expf(mp.w - M);
        float4 lp = *(float4*)&lpart[row*4];
        float lsum = w0*lp.x + w1*lp.y + w2*lp.z + w3*lp.w;
        size_t gbase = (size_t)(qb*64 + row) * 1024 + h*HDIM + db;
        #pragma unroll
        for (int j = 0; j < 4; j++) {
            int d = db + j*4;
            float4 a0 = *(float4*)&red[((size_t)0*64 + row)*68 + d];
            float4 a1 = *(float4*)&red[((size_t)1*64 + row)*68 + d];
            float4 a2 = *(float4*)&red[((size_t)2*64 + row)*68 + d];
            float4 a3 = *(float4*)&red[((size_t)3*64 + row)*68 + d];
            *(float4*)&g_po[sp][gbase + j*4] = make_float4(
                w0*a0.x + w1*a1.x + w2*a2.x + w3*a3.x,
                w0*a0.y + w1*a1.y + w2*a2.y + w3*a3.y,
                w0*a0.z + w1*a1.z + w2*a2.z + w3*a3.z,
                w0*a0.w + w1*a1.w + w2*a2.w + w3*a3.w);
        }
        if ((tid & 3) == 0) {
            g_pl[sp][(qb*64 + row)*16 + h] = lsum;
            g_pm[sp][(qb*64 + row)*16 + h] = M;
        }
    }
}

// ---------------- split-K combine (4 partials) -> c_ao fp16 ----------------
__global__ void attn_combine() {
    int gw = (blockIdx.x * blockDim.x + threadIdx.x) >> 5;
    int lane = threadIdx.x & 31;
    if (gw >= QLEN * NHEADS) return;
    int row = gw >> 4, h = gw & 15;
    int il = row * 16 + h;
    float m0 = g_pm[0][il], m1 = g_pm[1][il], m2 = g_pm[2][il], m3 = g_pm[3][il];
    float M = fmaxf(fmaxf(m0, m1), fmaxf(m2, m3));
    float w0 = __expf(m0 - M), w1 = __expf(m1 - M);
    float w2 = __expf(m2 - M), w3 = __expf(m3 - M);
    float l = w0*g_pl[0][il] + w1*g_pl[1][il] + w2*g_pl[2][il] + w3*g_pl[3][il];
    float inv = 1.0f / l;
    size_t base = (size_t)row * 1024 + h * HDIM;
    float2 a0 = *(float2*)&g_po[0][base + 2*lane];
    float2 a1 = *(float2*)&g_po[1][base + 2*lane];
    float2 a2 = *(float2*)&g_po[2][base + 2*lane];
    float2 a3 = *(float2*)&g_po[3][base + 2*lane];
    float v0 = (w0*a0.x + w1*a1.x + w2*a2.x + w3*a3.x) * inv;
    float v1 = (w0*a0.y + w1*a1.y + w2*a2.y + w3*a3.y) * inv;
    *(uint32_t*)&c_ao_f[base + 2*lane] = packh2(v0, v1);
}

// ---------------------------------------------------------------------------
extern "C" void kernel_launch(void* const* d_in, const int* in_sizes, int n_in,
                              void* d_out, int out_size) {
    const float* hidden = (const float*)d_in[0];
    const float* target = (const float*)d_in[1];
    const float* cosb   = (const float*)d_in[2];
    const float* sinb   = (const float*)d_in[3];
    const float* mask   = (const float*)d_in[4];
    const float* Wq     = (const float*)d_in[5];
    const float* Wk     = (const float*)d_in[6];
    const float* Wv     = (const float*)d_in[7];
    const float* Wo     = (const float*)d_in[8];
    const float* qw     = (const float*)d_in[9];
    const float* kw     = (const float*)d_in[10];
    const float* tb     = (const float*)d_in[11];
    const int*   rm     = (const int*)d_in[12];
    float* out = (float*)d_out;

    float *pq, *pk;
    cudaGetSymbolAddress((void**)&pq, g_q);
    cudaGetSymbolAddress((void**)&pk, g_k);

    __half *hidf,*wqf,*wof,*aof;
    cudaGetSymbolAddress((void**)&hidf, c_hid_f);
    cudaGetSymbolAddress((void**)&wqf,  c_wq_f);
    cudaGetSymbolAddress((void**)&wof,  c_wo_f);
    cudaGetSymbolAddress((void**)&aof,  c_ao_f);

    cvt_acts<<<((QLEN+CTXLEN)*HID/4 + 255)/256, 256>>>(hidden, target);
    cvt_wts<<<((HID*1024 + HID*512 + HID*512 + 1024*HID)/4 + 255)/256, 256>>>(Wq, Wk, Wv, Wo);

    cudaFuncSetAttribute(gemm_f1,   cudaFuncAttributeMaxDynamicSharedMemorySize, GEMM_SMEM_BYTES);
    cudaFuncSetAttribute(kvproj_f1, cudaFuncAttributeMaxDynamicSharedMemorySize, GEMM_SMEM_BYTES);

    gemm_f1<<<dim3(1024/128, QLEN/128), 256, GEMM_SMEM_BYTES>>>(hidf, wqf, pq, 1024, HID);
    kvproj_f1<<<dim3(512/128, QLEN/128, 4), 256, GEMM_SMEM_BYTES>>>(pk);

    norm_rope<<<8192, 256>>>(cosb, sinb, qw, kw);

    cudaFuncSetAttribute(attn_kernel, cudaFuncAttributeMaxDynamicSharedMemorySize, ATTN_SMEM_BYTES);
    attn_kernel<<<dim3(32, 16, NSPLIT), 256, ATTN_SMEM_BYTES>>>(mask, tb, rm);
    attn_combine<<<(QLEN*NHEADS*32 + 255)/256, 256>>>();

    gemm_f1<<<dim3(1024/128, QLEN/128), 256, GEMM_SMEM_BYTES>>>(aof, wof, out, 1024, HID);
}